// round 1
// baseline (speedup 1.0000x reference)
#include <cuda_runtime.h>
#include <cstdint>
#include <cstddef>

#define BB 2
#define NN 512
#define KK 128
#define EE 768

// output layout: edge_feature [B,N,N,K] | merge [B,N,E] | delta_pos [B,N,N,3]
#define OFF_EF    ((size_t)0)
#define OFF_MERGE ((size_t)BB*NN*NN*KK)                 // 67108864
#define OFF_DP    (OFF_MERGE + (size_t)BB*NN*EE)        // 67895296

// scratch (no allocations allowed)
__device__ __align__(16) float g_t2[BB][KK];   // 2 * t_enc(time_pos[b])
__device__ __align__(16) float g_t02[KK];      // 2 * t_enc(0)
__device__ __align__(16) float g_sum[BB*NN*KK];
__device__ int g_mask_is_byte;

__device__ __forceinline__ int maskv(const void* p, int idx, int isb) {
    return isb ? (int)((const unsigned char*)p)[idx] : ((const int*)p)[idx];
}

// ---------------------------------------------------------------------------
// Kernel 1: mask-format detection + timestep encoder MLP (tiny)
// ---------------------------------------------------------------------------
__global__ void tenc_kernel(const int* __restrict__ time_pos,
                            const float* __restrict__ w1, const float* __restrict__ b1,
                            const float* __restrict__ w2, const float* __restrict__ b2,
                            const void* __restrict__ pad_mask)
{
    __shared__ float es[KK], hs[KK];
    int tid = threadIdx.x;

    if (tid == 0) {
        // bool masks stored as bytes -> random 0/1 bytes make some 32-bit word > 1
        // int32 masks -> every word is exactly 0 or 1
        const unsigned int* w = (const unsigned int*)pad_mask;
        int f = 0;
        for (int i = 0; i < 256; i++) if (w[i] > 1u) f = 1;
        g_mask_is_byte = f;
    }

    for (int c = 0; c < 3; c++) {
        float tval = (c < 2) ? (float)time_pos[c] : 0.0f;
        int h = (tid < 64) ? tid : tid - 64;
        float fr  = __expf(-9.210340371976184f * (float)h * (1.0f / 64.0f));
        float arg = tval * fr;
        es[tid] = (tid < 64) ? cosf(arg) : sinf(arg);
        __syncthreads();

        float a = b1[tid];
        for (int k = 0; k < KK; k++) a = fmaf(es[k], w1[k * KK + tid], a);
        float sg = 1.0f / (1.0f + __expf(-a));
        hs[tid] = a * sg;                        // SiLU
        __syncthreads();

        float o = b2[tid];
        for (int k = 0; k < KK; k++) o = fmaf(hs[k], w2[k * KK + tid], o);
        o *= 2.0f;                               // pre-double (ref adds 2*t)
        if (c < 2) g_t2[c][tid] = o; else g_t02[tid] = o;
        __syncthreads();
    }
}

// ---------------------------------------------------------------------------
// Kernel 2: main edge kernel — one block per (b,i) row
// ---------------------------------------------------------------------------
__global__ void __launch_bounds__(128, 8) edge_kernel(
    const float* __restrict__ pos,
    const int*   __restrict__ nte,
    const void*  __restrict__ pad_m,
    const void*  __restrict__ aa_m,
    const void*  __restrict__ pos_m,
    const float* __restrict__ means,
    const float* __restrict__ stds,
    const float* __restrict__ mul_w,
    const float* __restrict__ bias_w,
    float* __restrict__ out)
{
    const int i = blockIdx.x;
    const int b = blockIdx.y;
    const int tid  = threadIdx.x;
    const int lane = tid & 31;
    const int warp = tid >> 5;
    const int isb  = g_mask_is_byte;

    __shared__ float4 pk[NN];          // (x, padf, mdf, -)
    __shared__ float  ppos[NN * 3];
    __shared__ float4 partial[4][32];

    for (int idx = tid; idx < NN * 3; idx += 128) ppos[idx] = pos[b * NN * 3 + idx];
    __syncthreads();

    const float pix = ppos[i * 3 + 0], piy = ppos[i * 3 + 1], piz = ppos[i * 3 + 2];
    const int aa_i = maskv(aa_m,  b * NN + i, isb);
    const int mp_i = maskv(pos_m, b * NN + i, isb);

    float* dpo = out + OFF_DP + ((size_t)(b * NN + i)) * (size_t)NN * 3;
    const int2* nrow = (const int2*)(nte + ((size_t)(b * NN + i)) * (size_t)NN * 2);

    // ---- Phase 1: per-j scalars -------------------------------------------
    for (int jt = tid; jt < NN; jt += 128) {
        float dx = ppos[jt * 3 + 0] - pix;
        float dy = ppos[jt * 3 + 1] - piy;
        float dz = ppos[jt * 3 + 2] - piz;
        float dist = sqrtf(dx * dx + dy * dy + dz * dz);
        float rinv = __fdividef(1.0f, dist + 1e-5f);
        dpo[jt * 3 + 0] = dx * rinv;
        dpo[jt * 3 + 1] = dy * rinv;
        dpo[jt * 3 + 2] = dz * rinv;

        int2 e2  = nrow[jt];
        int aa_j = maskv(aa_m, b * NN + jt, isb);
        int n0 = aa_i ? 0 : e2.x;
        int n1 = aa_j ? 0 : e2.y;
        float mul = mul_w[n0]  + mul_w[n1];
        float bia = bias_w[n0] + bias_w[n1];

        int padj = maskv(pad_m, b * NN + jt, isb);
        int md   = mp_i | maskv(pos_m, b * NN + jt, isb);
        pk[jt] = make_float4(fmaf(mul, dist, bia),
                             padj ? 0.0f : 1.0f,
                             md   ? 1.0f : 0.0f, 0.0f);
    }
    __syncthreads();

    // ---- per-thread k-quad parameters -------------------------------------
    const int k0 = lane * 4;
    float4 mn = *(const float4*)(means + k0);
    float4 sd = *(const float4*)(stds + k0);
    float is_x = 1.0f / (fabsf(sd.x) + 0.01f);
    float is_y = 1.0f / (fabsf(sd.y) + 0.01f);
    float is_z = 1.0f / (fabsf(sd.z) + 0.01f);
    float is_w = 1.0f / (fabsf(sd.w) + 0.01f);
    const float inv_a = 0.39894290f;           // 1/sqrt(2*3.14159)
    float cf_x = is_x * inv_a, cf_y = is_y * inv_a, cf_z = is_z * inv_a, cf_w = is_w * inv_a;
    float mi_x = mn.x * is_x, mi_y = mn.y * is_y, mi_z = mn.z * is_z, mi_w = mn.w * is_w;

    float4 t2v  = *(const float4*)(&g_t2[b][k0]);
    float4 t02v = *(const float4*)(&g_t02[k0]);
    float dt_x = t2v.x - t02v.x, dt_y = t2v.y - t02v.y;
    float dt_z = t2v.z - t02v.z, dt_w = t2v.w - t02v.w;

    float* efb = out + OFF_EF + ((size_t)(b * NN + i)) * (size_t)(NN * KK);
    float4 acc = make_float4(0.f, 0.f, 0.f, 0.f);

    // ---- Phase 2: main loop — warp owns j%4, lane owns k-quad --------------
    #pragma unroll 2
    for (int jb = 0; jb < NN / 4; jb++) {
        int j = jb * 4 + warp;
        float4 p = pk[j];
        float x = p.x, padf = p.y, mdf = p.z;

        float zx = fmaf(x, is_x, -mi_x);
        float zy = fmaf(x, is_y, -mi_y);
        float zz = fmaf(x, is_z, -mi_z);
        float zw = fmaf(x, is_w, -mi_w);
        float gx = __expf(zx * zx * -0.5f);
        float gy = __expf(zy * zy * -0.5f);
        float gz = __expf(zz * zz * -0.5f);
        float gw = __expf(zw * zw * -0.5f);

        float4 r;
        r.x = padf * fmaf(gx, cf_x, fmaf(mdf, dt_x, t02v.x));
        r.y = padf * fmaf(gy, cf_y, fmaf(mdf, dt_y, t02v.y));
        r.z = padf * fmaf(gz, cf_z, fmaf(mdf, dt_z, t02v.z));
        r.w = padf * fmaf(gw, cf_w, fmaf(mdf, dt_w, t02v.w));

        acc.x += r.x; acc.y += r.y; acc.z += r.z; acc.w += r.w;
        *(float4*)(efb + (size_t)j * KK + k0) = r;
    }

    // ---- row-sum reduction across the 4 warps ------------------------------
    partial[warp][lane] = acc;
    __syncthreads();
    if (warp == 0) {
        float4 a0 = partial[0][lane], a1 = partial[1][lane];
        float4 a2 = partial[2][lane], a3 = partial[3][lane];
        float4 s = make_float4(a0.x + a1.x + a2.x + a3.x,
                               a0.y + a1.y + a2.y + a3.y,
                               a0.z + a1.z + a2.z + a3.z,
                               a0.w + a1.w + a2.w + a3.w);
        *(float4*)(&g_sum[((size_t)(b * NN + i)) * KK + k0]) = s;
    }
}

// ---------------------------------------------------------------------------
// Kernel 3: merge = sum_edge_features @ proj_w + proj_b (zero padded rows)
// grid (64, 3): 16-row tiles x 256-col tiles
// ---------------------------------------------------------------------------
__global__ void __launch_bounds__(256) proj_kernel(
    const float* __restrict__ pw, const float* __restrict__ pb,
    const void* __restrict__ pad_m, float* __restrict__ out)
{
    __shared__ float s[16 * KK];
    const int bx  = blockIdx.x;
    const int e   = blockIdx.y * 256 + threadIdx.x;
    const int tid = threadIdx.x;

    for (int idx = tid; idx < 16 * KK; idx += 256)
        s[idx] = g_sum[(size_t)bx * 16 * KK + idx];
    __syncthreads();

    float acc[16];
    #pragma unroll
    for (int ii = 0; ii < 16; ii++) acc[ii] = 0.0f;

    for (int k = 0; k < KK; k++) {
        float w = pw[(size_t)k * EE + e];
        #pragma unroll
        for (int ii = 0; ii < 16; ii++) acc[ii] = fmaf(s[ii * KK + k], w, acc[ii]);
    }

    float bias = pb[e];
    int isb = g_mask_is_byte;
    #pragma unroll
    for (int ii = 0; ii < 16; ii++) {
        int row = bx * 16 + ii;                      // row = b*N + i
        int pm = maskv(pad_m, row, isb);
        out[OFF_MERGE + (size_t)row * EE + e] = pm ? 0.0f : (acc[ii] + bias);
    }
}

// ---------------------------------------------------------------------------
extern "C" void kernel_launch(void* const* d_in, const int* in_sizes, int n_in,
                              void* d_out, int out_size)
{
    const float* pos    = (const float*)d_in[0];
    const int*   nte    = (const int*)  d_in[1];
    const void*  pad_m  = d_in[2];
    const void*  aa_m   = d_in[3];
    const void*  pos_m  = d_in[4];
    const int*   time_p = (const int*)  d_in[5];
    const float* means  = (const float*)d_in[6];
    const float* stds   = (const float*)d_in[7];
    const float* mul_w  = (const float*)d_in[8];
    const float* bias_w = (const float*)d_in[9];
    const float* proj_w = (const float*)d_in[10];
    const float* proj_b = (const float*)d_in[11];
    const float* t_w1   = (const float*)d_in[12];
    const float* t_b1   = (const float*)d_in[13];
    const float* t_w2   = (const float*)d_in[14];
    const float* t_b2   = (const float*)d_in[15];
    float* out = (float*)d_out;

    tenc_kernel<<<1, 128>>>(time_p, t_w1, t_b1, t_w2, t_b2, pad_m);
    edge_kernel<<<dim3(NN, BB), 128>>>(pos, nte, pad_m, aa_m, pos_m,
                                       means, stds, mul_w, bias_w, out);
    proj_kernel<<<dim3((BB * NN) / 16, EE / 256), 256>>>(proj_w, proj_b, pad_m, out);
}

// round 3
// speedup vs baseline: 1.1875x; 1.1875x over previous
#include <cuda_runtime.h>
#include <cstdint>
#include <cstddef>

#define BB 2
#define NN 512
#define KK 128
#define EE 768

// output layout: edge_feature [B,N,N,K] | merge [B,N,E] | delta_pos [B,N,N,3]
#define OFF_EF    ((size_t)0)
#define OFF_MERGE ((size_t)BB*NN*NN*KK)                 // 67108864
#define OFF_DP    (OFF_MERGE + (size_t)BB*NN*EE)        // 67895296

// scratch (no allocations allowed)
__device__ __align__(16) float g_t2[BB][KK];   // 2 * t_enc(time_pos[b])
__device__ __align__(16) float g_t02[KK];      // 2 * t_enc(0)
__device__ __align__(16) float g_sum[BB*NN*KK];
__device__ int g_mask_is_byte;

__device__ __forceinline__ int maskv(const void* p, int idx, int isb) {
    return isb ? (int)((const unsigned char*)p)[idx] : ((const int*)p)[idx];
}

// ---------------------------------------------------------------------------
// Kernel 1: timestep encoder MLP — 3 blocks (c = 0,1,2), high-MLP matvecs
// ---------------------------------------------------------------------------
__global__ void __launch_bounds__(128) tenc_kernel(
    const int* __restrict__ time_pos,
    const float* __restrict__ w1, const float* __restrict__ b1,
    const float* __restrict__ w2, const float* __restrict__ b2,
    const void* __restrict__ pad_mask)
{
    __shared__ float es[KK], hs[KK];
    const int tid = threadIdx.x;
    const int c = blockIdx.x;

    // mask-format detection: bool masks stored as bytes -> some 32-bit word of
    // the first 1024 bytes is > 1; int32 masks -> every word is 0 or 1.
    {
        const unsigned int* w = (const unsigned int*)pad_mask;
        int f = (w[tid] > 1u) | (w[tid + 128] > 1u);
        int any = __syncthreads_or(f);
        if (tid == 0) g_mask_is_byte = any ? 1 : 0;
    }

    float tval = (c < 2) ? (float)time_pos[c] : 0.0f;
    int h = (tid < 64) ? tid : tid - 64;
    float fr  = __expf(-9.210340371976184f * (float)h * (1.0f / 64.0f));
    float arg = tval * fr;
    es[tid] = (tid < 64) ? cosf(arg) : sinf(arg);
    __syncthreads();

    // layer 1: out[tid] = silu(es . w1[:,tid] + b1[tid])
    {
        float a0 = 0.f, a1 = 0.f, a2 = 0.f, a3 = 0.f;
        #pragma unroll
        for (int k = 0; k < KK; k += 4) {
            a0 = fmaf(es[k + 0], w1[(k + 0) * KK + tid], a0);
            a1 = fmaf(es[k + 1], w1[(k + 1) * KK + tid], a1);
            a2 = fmaf(es[k + 2], w1[(k + 2) * KK + tid], a2);
            a3 = fmaf(es[k + 3], w1[(k + 3) * KK + tid], a3);
        }
        float a = b1[tid] + ((a0 + a1) + (a2 + a3));
        float sg = 1.0f / (1.0f + __expf(-a));
        hs[tid] = a * sg;                        // SiLU
    }
    __syncthreads();

    // layer 2
    {
        float a0 = 0.f, a1 = 0.f, a2 = 0.f, a3 = 0.f;
        #pragma unroll
        for (int k = 0; k < KK; k += 4) {
            a0 = fmaf(hs[k + 0], w2[(k + 0) * KK + tid], a0);
            a1 = fmaf(hs[k + 1], w2[(k + 1) * KK + tid], a1);
            a2 = fmaf(hs[k + 2], w2[(k + 2) * KK + tid], a2);
            a3 = fmaf(hs[k + 3], w2[(k + 3) * KK + tid], a3);
        }
        float o = (b2[tid] + ((a0 + a1) + (a2 + a3))) * 2.0f;  // pre-double
        if (c < 2) g_t2[c][tid] = o; else g_t02[tid] = o;
    }
}

// ---------------------------------------------------------------------------
// Kernel 2: main edge kernel — one block per (b,i) row, 256 threads (8 warps)
// ---------------------------------------------------------------------------
__global__ void __launch_bounds__(256) edge_kernel(
    const float* __restrict__ pos,
    const int*   __restrict__ nte,
    const void*  __restrict__ pad_m,
    const void*  __restrict__ aa_m,
    const void*  __restrict__ pos_m,
    const float* __restrict__ means,
    const float* __restrict__ stds,
    const float* __restrict__ mul_w,
    const float* __restrict__ bias_w,
    float* __restrict__ out)
{
    const int i = blockIdx.x;
    const int b = blockIdx.y;
    const int tid  = threadIdx.x;
    const int lane = tid & 31;
    const int warp = tid >> 5;
    const int isb  = g_mask_is_byte;

    __shared__ float4 pk[NN];          // (x, padf, mdf, -)
    __shared__ float  ppos[NN * 3];
    __shared__ float4 partial[8][32];

    for (int idx = tid; idx < NN * 3; idx += 256) ppos[idx] = pos[b * NN * 3 + idx];
    __syncthreads();

    const float pix = ppos[i * 3 + 0], piy = ppos[i * 3 + 1], piz = ppos[i * 3 + 2];
    const int aa_i = maskv(aa_m,  b * NN + i, isb);
    const int mp_i = maskv(pos_m, b * NN + i, isb);

    float* dpo = out + OFF_DP + ((size_t)(b * NN + i)) * (size_t)NN * 3;
    const int2* nrow = (const int2*)(nte + ((size_t)(b * NN + i)) * (size_t)NN * 2);

    // ---- Phase 1: per-j scalars -------------------------------------------
    for (int jt = tid; jt < NN; jt += 256) {
        float dx = ppos[jt * 3 + 0] - pix;
        float dy = ppos[jt * 3 + 1] - piy;
        float dz = ppos[jt * 3 + 2] - piz;
        float dist = sqrtf(dx * dx + dy * dy + dz * dz);
        float rinv = __fdividef(1.0f, dist + 1e-5f);
        dpo[jt * 3 + 0] = dx * rinv;
        dpo[jt * 3 + 1] = dy * rinv;
        dpo[jt * 3 + 2] = dz * rinv;

        int2 e2  = nrow[jt];
        int aa_j = maskv(aa_m, b * NN + jt, isb);
        int n0 = aa_i ? 0 : e2.x;
        int n1 = aa_j ? 0 : e2.y;
        float mul = mul_w[n0]  + mul_w[n1];
        float bia = bias_w[n0] + bias_w[n1];

        int padj = maskv(pad_m, b * NN + jt, isb);
        int md   = mp_i | maskv(pos_m, b * NN + jt, isb);
        pk[jt] = make_float4(fmaf(mul, dist, bia),
                             padj ? 0.0f : 1.0f,
                             md   ? 1.0f : 0.0f, 0.0f);
    }
    __syncthreads();

    // ---- per-thread k-quad parameters -------------------------------------
    const int k0 = lane * 4;
    float4 mn = *(const float4*)(means + k0);
    float4 sd = *(const float4*)(stds + k0);
    float is_x = 1.0f / (fabsf(sd.x) + 0.01f);
    float is_y = 1.0f / (fabsf(sd.y) + 0.01f);
    float is_z = 1.0f / (fabsf(sd.z) + 0.01f);
    float is_w = 1.0f / (fabsf(sd.w) + 0.01f);
    const float inv_a = 0.39894290f;           // 1/sqrt(2*3.14159)
    float cf_x = is_x * inv_a, cf_y = is_y * inv_a, cf_z = is_z * inv_a, cf_w = is_w * inv_a;
    float mi_x = mn.x * is_x, mi_y = mn.y * is_y, mi_z = mn.z * is_z, mi_w = mn.w * is_w;

    float4 t2v  = *(const float4*)(&g_t2[b][k0]);
    float4 t02v = *(const float4*)(&g_t02[k0]);
    float dt_x = t2v.x - t02v.x, dt_y = t2v.y - t02v.y;
    float dt_z = t2v.z - t02v.z, dt_w = t2v.w - t02v.w;

    float* efb = out + OFF_EF + ((size_t)(b * NN + i)) * (size_t)(NN * KK);
    float4 acc = make_float4(0.f, 0.f, 0.f, 0.f);

    // ---- Phase 2: main loop — warp owns j%8, lane owns k-quad --------------
    #pragma unroll 4
    for (int jb = 0; jb < NN / 8; jb++) {
        int j = jb * 8 + warp;
        float4 p = pk[j];
        float x = p.x, padf = p.y, mdf = p.z;

        float zx = fmaf(x, is_x, -mi_x);
        float zy = fmaf(x, is_y, -mi_y);
        float zz = fmaf(x, is_z, -mi_z);
        float zw = fmaf(x, is_w, -mi_w);
        float gx = __expf(zx * zx * -0.5f);
        float gy = __expf(zy * zy * -0.5f);
        float gz = __expf(zz * zz * -0.5f);
        float gw = __expf(zw * zw * -0.5f);

        float4 r;
        r.x = padf * fmaf(gx, cf_x, fmaf(mdf, dt_x, t02v.x));
        r.y = padf * fmaf(gy, cf_y, fmaf(mdf, dt_y, t02v.y));
        r.z = padf * fmaf(gz, cf_z, fmaf(mdf, dt_z, t02v.z));
        r.w = padf * fmaf(gw, cf_w, fmaf(mdf, dt_w, t02v.w));

        acc.x += r.x; acc.y += r.y; acc.z += r.z; acc.w += r.w;
        *(float4*)(efb + (size_t)j * KK + k0) = r;
    }

    // ---- row-sum reduction across the 8 warps ------------------------------
    partial[warp][lane] = acc;
    __syncthreads();
    if (warp == 0) {
        float4 s = make_float4(0.f, 0.f, 0.f, 0.f);
        #pragma unroll
        for (int w = 0; w < 8; w++) {
            float4 a = partial[w][lane];
            s.x += a.x; s.y += a.y; s.z += a.z; s.w += a.w;
        }
        *(float4*)(&g_sum[((size_t)(b * NN + i)) * KK + k0]) = s;
    }
}

// ---------------------------------------------------------------------------
// Kernel 3: merge = sum_edge_features @ proj_w + proj_b (zero padded rows)
// grid (64, 3): 16-row tiles x 256-col tiles
// ---------------------------------------------------------------------------
__global__ void __launch_bounds__(256) proj_kernel(
    const float* __restrict__ pw, const float* __restrict__ pb,
    const void* __restrict__ pad_m, float* __restrict__ out)
{
    __shared__ float s[16 * KK];
    const int bx  = blockIdx.x;
    const int e   = blockIdx.y * 256 + threadIdx.x;
    const int tid = threadIdx.x;

    for (int idx = tid; idx < 16 * KK; idx += 256)
        s[idx] = g_sum[(size_t)bx * 16 * KK + idx];
    __syncthreads();

    float acc[16];
    #pragma unroll
    for (int ii = 0; ii < 16; ii++) acc[ii] = 0.0f;

    for (int k = 0; k < KK; k++) {
        float w = pw[(size_t)k * EE + e];
        #pragma unroll
        for (int ii = 0; ii < 16; ii++) acc[ii] = fmaf(s[ii * KK + k], w, acc[ii]);
    }

    float bias = pb[e];
    int isb = g_mask_is_byte;
    #pragma unroll
    for (int ii = 0; ii < 16; ii++) {
        int row = bx * 16 + ii;                      // row = b*N + i
        int pm = maskv(pad_m, row, isb);
        out[OFF_MERGE + (size_t)row * EE + e] = pm ? 0.0f : (acc[ii] + bias);
    }
}

// ---------------------------------------------------------------------------
extern "C" void kernel_launch(void* const* d_in, const int* in_sizes, int n_in,
                              void* d_out, int out_size)
{
    const float* pos    = (const float*)d_in[0];
    const int*   nte    = (const int*)  d_in[1];
    const void*  pad_m  = d_in[2];
    const void*  aa_m   = d_in[3];
    const void*  pos_m  = d_in[4];
    const int*   time_p = (const int*)  d_in[5];
    const float* means  = (const float*)d_in[6];
    const float* stds   = (const float*)d_in[7];
    const float* mul_w  = (const float*)d_in[8];
    const float* bias_w = (const float*)d_in[9];
    const float* proj_w = (const float*)d_in[10];
    const float* proj_b = (const float*)d_in[11];
    const float* t_w1   = (const float*)d_in[12];
    const float* t_b1   = (const float*)d_in[13];
    const float* t_w2   = (const float*)d_in[14];
    const float* t_b2   = (const float*)d_in[15];
    float* out = (float*)d_out;

    tenc_kernel<<<3, 128>>>(time_p, t_w1, t_b1, t_w2, t_b2, pad_m);
    edge_kernel<<<dim3(NN, BB), 256>>>(pos, nte, pad_m, aa_m, pos_m,
                                       means, stds, mul_w, bias_w, out);
    proj_kernel<<<dim3((BB * NN) / 16, EE / 256), 256>>>(proj_w, proj_b, pad_m, out);
}

// round 4
// speedup vs baseline: 1.4179x; 1.1940x over previous
#include <cuda_runtime.h>
#include <cstdint>
#include <cstddef>

#define BB 2
#define NN 512
#define KK 128
#define EE 768

// output layout: edge_feature [B,N,N,K] | merge [B,N,E] | delta_pos [B,N,N,3]
#define OFF_EF    ((size_t)0)
#define OFF_MERGE ((size_t)BB*NN*NN*KK)                 // 67108864
#define OFF_DP    (OFF_MERGE + (size_t)BB*NN*EE)        // 67895296

__device__ __align__(16) float g_t2[BB][KK];   // 2 * t_enc(time_pos[b])
__device__ __align__(16) float g_t02[KK];      // 2 * t_enc(0)
__device__ __align__(16) float g_sum[BB*NN*KK];
__device__ int g_mask_is_byte;

__device__ __forceinline__ int maskv(const void* p, int idx, int isb) {
    return isb ? (int)((const unsigned char*)p)[idx] : ((const int*)p)[idx];
}

// ---------------------------------------------------------------------------
// Kernel 1: timestep encoder MLP — split-K: 4 threads per output, 32 loads each
// grid = 3 (c = t(b0), t(b1), t(0)), block = 512
// ---------------------------------------------------------------------------
__global__ void __launch_bounds__(512) tenc_kernel(
    const int* __restrict__ time_pos,
    const float* __restrict__ w1, const float* __restrict__ b1,
    const float* __restrict__ w2, const float* __restrict__ b2,
    const void* __restrict__ pad_mask)
{
    __shared__ float es[KK], hs[KK];
    const int tid = threadIdx.x;
    const int c = blockIdx.x;
    const int o = tid >> 2;          // output index 0..127
    const int q = tid & 3;           // k-quarter 0..3

    // mask-format detection: bool-as-bytes -> some 32-bit word in first 1KB > 1
    {
        int f = 0;
        if (tid < 256) f = (((const unsigned int*)pad_mask)[tid] > 1u);
        int any = __syncthreads_or(f);
        if (tid == 0) g_mask_is_byte = any ? 1 : 0;
    }

    if (tid < KK) {
        float tval = (c < 2) ? (float)time_pos[c] : 0.0f;
        int h = (tid < 64) ? tid : tid - 64;
        float fr  = __expf(-9.210340371976184f * (float)h * (1.0f / 64.0f));
        float arg = tval * fr;
        es[tid] = (tid < 64) ? cosf(arg) : sinf(arg);
    }
    __syncthreads();

    // layer 1
    {
        const float* wcol = w1 + (q * 32) * KK + o;
        float a0 = 0.f, a1 = 0.f, a2 = 0.f, a3 = 0.f;
        #pragma unroll
        for (int kk = 0; kk < 32; kk += 4) {
            a0 = fmaf(es[q * 32 + kk + 0], wcol[(kk + 0) * KK], a0);
            a1 = fmaf(es[q * 32 + kk + 1], wcol[(kk + 1) * KK], a1);
            a2 = fmaf(es[q * 32 + kk + 2], wcol[(kk + 2) * KK], a2);
            a3 = fmaf(es[q * 32 + kk + 3], wcol[(kk + 3) * KK], a3);
        }
        float r = (a0 + a1) + (a2 + a3);
        r += __shfl_xor_sync(0xffffffffu, r, 1);
        r += __shfl_xor_sync(0xffffffffu, r, 2);
        if (q == 0) {
            float a = r + b1[o];
            float sg = 1.0f / (1.0f + __expf(-a));
            hs[o] = a * sg;                      // SiLU
        }
    }
    __syncthreads();

    // layer 2
    {
        const float* wcol = w2 + (q * 32) * KK + o;
        float a0 = 0.f, a1 = 0.f, a2 = 0.f, a3 = 0.f;
        #pragma unroll
        for (int kk = 0; kk < 32; kk += 4) {
            a0 = fmaf(hs[q * 32 + kk + 0], wcol[(kk + 0) * KK], a0);
            a1 = fmaf(hs[q * 32 + kk + 1], wcol[(kk + 1) * KK], a1);
            a2 = fmaf(hs[q * 32 + kk + 2], wcol[(kk + 2) * KK], a2);
            a3 = fmaf(hs[q * 32 + kk + 3], wcol[(kk + 3) * KK], a3);
        }
        float r = (a0 + a1) + (a2 + a3);
        r += __shfl_xor_sync(0xffffffffu, r, 1);
        r += __shfl_xor_sync(0xffffffffu, r, 2);
        if (q == 0) {
            float oo = (r + b2[o]) * 2.0f;       // pre-double
            if (c < 2) g_t2[c][o] = oo; else g_t02[o] = oo;
        }
    }
}

// ---------------------------------------------------------------------------
// Kernel 2: main edge kernel — one block per (b,i) row, 256 threads (8 warps)
// ---------------------------------------------------------------------------
__global__ void __launch_bounds__(256) edge_kernel(
    const float* __restrict__ pos,
    const int*   __restrict__ nte,
    const void*  __restrict__ pad_m,
    const void*  __restrict__ aa_m,
    const void*  __restrict__ pos_m,
    const float* __restrict__ means,
    const float* __restrict__ stds,
    const float* __restrict__ mul_w,
    const float* __restrict__ bias_w,
    float* __restrict__ out)
{
    const int i = blockIdx.x;
    const int b = blockIdx.y;
    const int tid  = threadIdx.x;
    const int lane = tid & 31;
    const int warp = tid >> 5;
    const int isb  = g_mask_is_byte;

    __shared__ float4 pk[NN];          // (x, padf, mdf, -)
    __shared__ float  ppos[NN * 3];
    __shared__ float4 partial[8][32];

    for (int idx = tid; idx < NN * 3; idx += 256) ppos[idx] = pos[b * NN * 3 + idx];
    __syncthreads();

    const float pix = ppos[i * 3 + 0], piy = ppos[i * 3 + 1], piz = ppos[i * 3 + 2];
    const int aa_i = maskv(aa_m,  b * NN + i, isb);
    const int mp_i = maskv(pos_m, b * NN + i, isb);

    float* dpo = out + OFF_DP + ((size_t)(b * NN + i)) * (size_t)NN * 3;
    const int2* nrow = (const int2*)(nte + ((size_t)(b * NN + i)) * (size_t)NN * 2);

    // ---- Phase 1: per-j scalars -------------------------------------------
    for (int jt = tid; jt < NN; jt += 256) {
        float dx = ppos[jt * 3 + 0] - pix;
        float dy = ppos[jt * 3 + 1] - piy;
        float dz = ppos[jt * 3 + 2] - piz;
        float dist = sqrtf(dx * dx + dy * dy + dz * dz);
        float rinv = __fdividef(1.0f, dist + 1e-5f);
        dpo[jt * 3 + 0] = dx * rinv;
        dpo[jt * 3 + 1] = dy * rinv;
        dpo[jt * 3 + 2] = dz * rinv;

        int2 e2  = nrow[jt];
        int aa_j = maskv(aa_m, b * NN + jt, isb);
        int n0 = aa_i ? 0 : e2.x;
        int n1 = aa_j ? 0 : e2.y;
        float mul = mul_w[n0]  + mul_w[n1];
        float bia = bias_w[n0] + bias_w[n1];

        int padj = maskv(pad_m, b * NN + jt, isb);
        int md   = mp_i | maskv(pos_m, b * NN + jt, isb);
        pk[jt] = make_float4(fmaf(mul, dist, bia),
                             padj ? 0.0f : 1.0f,
                             md   ? 1.0f : 0.0f, 0.0f);
    }
    __syncthreads();

    // ---- per-thread k-quad parameters -------------------------------------
    const int k0 = lane * 4;
    float4 mn = *(const float4*)(means + k0);
    float4 sd = *(const float4*)(stds + k0);
    float is_x = 1.0f / (fabsf(sd.x) + 0.01f);
    float is_y = 1.0f / (fabsf(sd.y) + 0.01f);
    float is_z = 1.0f / (fabsf(sd.z) + 0.01f);
    float is_w = 1.0f / (fabsf(sd.w) + 0.01f);
    const float inv_a = 0.39894290f;           // 1/sqrt(2*3.14159)
    float cf_x = is_x * inv_a, cf_y = is_y * inv_a, cf_z = is_z * inv_a, cf_w = is_w * inv_a;
    float mi_x = mn.x * is_x, mi_y = mn.y * is_y, mi_z = mn.z * is_z, mi_w = mn.w * is_w;

    float4 t2v  = *(const float4*)(&g_t2[b][k0]);
    float4 t02v = *(const float4*)(&g_t02[k0]);
    float dt_x = t2v.x - t02v.x, dt_y = t2v.y - t02v.y;
    float dt_z = t2v.z - t02v.z, dt_w = t2v.w - t02v.w;

    float* efb = out + OFF_EF + ((size_t)(b * NN + i)) * (size_t)(NN * KK);
    float4 acc = make_float4(0.f, 0.f, 0.f, 0.f);
    const float4 zero4 = make_float4(0.f, 0.f, 0.f, 0.f);

    // ---- Phase 2: warp owns j%8, lane owns k-quad. Branch is warp-uniform. --
    #pragma unroll 4
    for (int jb = 0; jb < NN / 8; jb++) {
        int j = jb * 8 + warp;
        float4 p = pk[j];
        float4* dst = (float4*)(efb + (size_t)j * KK + k0);

        if (p.y == 0.0f) {
            // padded j-column: entire K row is zero — skip all math
            __stcs(dst, zero4);
        } else {
            float x = p.x, mdf = p.z;

            float zx = fmaf(x, is_x, -mi_x);
            float zy = fmaf(x, is_y, -mi_y);
            float zz = fmaf(x, is_z, -mi_z);
            float zw = fmaf(x, is_w, -mi_w);
            float gx = __expf(zx * zx * -0.5f);
            float gy = __expf(zy * zy * -0.5f);
            float gz = __expf(zz * zz * -0.5f);
            float gw = __expf(zw * zw * -0.5f);

            float4 r;
            r.x = fmaf(gx, cf_x, fmaf(mdf, dt_x, t02v.x));
            r.y = fmaf(gy, cf_y, fmaf(mdf, dt_y, t02v.y));
            r.z = fmaf(gz, cf_z, fmaf(mdf, dt_z, t02v.z));
            r.w = fmaf(gw, cf_w, fmaf(mdf, dt_w, t02v.w));

            acc.x += r.x; acc.y += r.y; acc.z += r.z; acc.w += r.w;
            __stcs(dst, r);
        }
    }

    // ---- row-sum reduction across the 8 warps ------------------------------
    partial[warp][lane] = acc;
    __syncthreads();
    if (warp == 0) {
        float4 s = make_float4(0.f, 0.f, 0.f, 0.f);
        #pragma unroll
        for (int w = 0; w < 8; w++) {
            float4 a = partial[w][lane];
            s.x += a.x; s.y += a.y; s.z += a.z; s.w += a.w;
        }
        *(float4*)(&g_sum[((size_t)(b * NN + i)) * KK + k0]) = s;
    }
}

// ---------------------------------------------------------------------------
// Kernel 3: merge = sum_edge_features @ proj_w + proj_b (zero padded rows)
// ---------------------------------------------------------------------------
__global__ void __launch_bounds__(256) proj_kernel(
    const float* __restrict__ pw, const float* __restrict__ pb,
    const void* __restrict__ pad_m, float* __restrict__ out)
{
    __shared__ float s[16 * KK];
    const int bx  = blockIdx.x;
    const int e   = blockIdx.y * 256 + threadIdx.x;
    const int tid = threadIdx.x;

    for (int idx = tid; idx < 16 * KK; idx += 256)
        s[idx] = g_sum[(size_t)bx * 16 * KK + idx];
    __syncthreads();

    float acc[16];
    #pragma unroll
    for (int ii = 0; ii < 16; ii++) acc[ii] = 0.0f;

    for (int k = 0; k < KK; k++) {
        float w = pw[(size_t)k * EE + e];
        #pragma unroll
        for (int ii = 0; ii < 16; ii++) acc[ii] = fmaf(s[ii * KK + k], w, acc[ii]);
    }

    float bias = pb[e];
    int isb = g_mask_is_byte;
    #pragma unroll
    for (int ii = 0; ii < 16; ii++) {
        int row = bx * 16 + ii;                      // row = b*N + i
        int pm = maskv(pad_m, row, isb);
        out[OFF_MERGE + (size_t)row * EE + e] = pm ? 0.0f : (acc[ii] + bias);
    }
}

// ---------------------------------------------------------------------------
extern "C" void kernel_launch(void* const* d_in, const int* in_sizes, int n_in,
                              void* d_out, int out_size)
{
    const float* pos    = (const float*)d_in[0];
    const int*   nte    = (const int*)  d_in[1];
    const void*  pad_m  = d_in[2];
    const void*  aa_m   = d_in[3];
    const void*  pos_m  = d_in[4];
    const int*   time_p = (const int*)  d_in[5];
    const float* means  = (const float*)d_in[6];
    const float* stds   = (const float*)d_in[7];
    const float* mul_w  = (const float*)d_in[8];
    const float* bias_w = (const float*)d_in[9];
    const float* proj_w = (const float*)d_in[10];
    const float* proj_b = (const float*)d_in[11];
    const float* t_w1   = (const float*)d_in[12];
    const float* t_b1   = (const float*)d_in[13];
    const float* t_w2   = (const float*)d_in[14];
    const float* t_b2   = (const float*)d_in[15];
    float* out = (float*)d_out;

    tenc_kernel<<<3, 512>>>(time_p, t_w1, t_b1, t_w2, t_b2, pad_m);
    edge_kernel<<<dim3(NN, BB), 256>>>(pos, nte, pad_m, aa_m, pos_m,
                                       means, stds, mul_w, bias_w, out);
    proj_kernel<<<dim3((BB * NN) / 16, EE / 256), 256>>>(proj_w, proj_b, pad_m, out);
}

// round 5
// speedup vs baseline: 1.4961x; 1.0551x over previous
#include <cuda_runtime.h>
#include <cstdint>
#include <cstddef>

#define BB 2
#define NN 512
#define KK 128
#define EE 768
#define NEDGE 1536

// output layout: edge_feature [B,N,N,K] | merge [B,N,E] | delta_pos [B,N,N,3]
#define OFF_EF    ((size_t)0)
#define OFF_MERGE ((size_t)BB*NN*NN*KK)                 // 67108864
#define OFF_DP    (OFF_MERGE + (size_t)BB*NN*EE)        // 67895296

__device__ __align__(16) float g_t2[BB][KK];   // 2 * t_enc(time_pos[b])
__device__ __align__(16) float g_t02[KK];      // 2 * t_enc(0)
__device__ __align__(16) float g_sum[BB*NN*KK];
__device__ int g_mask_is_byte;

__device__ __forceinline__ int maskv(const void* p, int idx, int isb) {
    return isb ? (int)((const unsigned char*)p)[idx] : ((const int*)p)[idx];
}

// ---------------------------------------------------------------------------
// Kernel 1: timestep encoder MLP — coalesced split-K.
// grid = 3 (c = t(b0), t(b1), t(0)), block = 512.
// thread: o = tid & 127 (output col), sl = tid >> 7 (k-slice of 32).
// For fixed k, a warp's 32 lanes read 32 consecutive columns -> 128B coalesced.
// ---------------------------------------------------------------------------
__global__ void __launch_bounds__(512) tenc_kernel(
    const int* __restrict__ time_pos,
    const float* __restrict__ w1, const float* __restrict__ b1,
    const float* __restrict__ w2, const float* __restrict__ b2,
    const void* __restrict__ pad_mask)
{
    __shared__ float es[KK], hs[KK];
    __shared__ float red[4][KK];
    const int tid = threadIdx.x;
    const int c  = blockIdx.x;
    const int o  = tid & 127;
    const int sl = tid >> 7;

    // mask-format detection: bool-as-bytes -> some 32-bit word in first 1KB > 1
    {
        int f = 0;
        if (tid < 256) f = (((const unsigned int*)pad_mask)[tid] > 1u);
        int any = __syncthreads_or(f);
        if (tid == 0 && c == 0) g_mask_is_byte = any ? 1 : 0;
    }

    if (tid < KK) {
        float tval = (c < 2) ? (float)time_pos[c] : 0.0f;
        int h = (tid < 64) ? tid : tid - 64;
        float fr  = __expf(-9.210340371976184f * (float)h * (1.0f / 64.0f));
        float arg = tval * fr;
        es[tid] = (tid < 64) ? cosf(arg) : sinf(arg);
    }
    __syncthreads();

    // layer 1: hs[o] = silu(es . w1[:,o] + b1[o])
    {
        const float* wc = w1 + (sl * 32) * KK + o;
        const float* ec = es + sl * 32;
        float a0 = 0.f, a1 = 0.f, a2 = 0.f, a3 = 0.f;
        #pragma unroll
        for (int kk = 0; kk < 32; kk += 4) {
            a0 = fmaf(ec[kk + 0], wc[(kk + 0) * KK], a0);
            a1 = fmaf(ec[kk + 1], wc[(kk + 1) * KK], a1);
            a2 = fmaf(ec[kk + 2], wc[(kk + 2) * KK], a2);
            a3 = fmaf(ec[kk + 3], wc[(kk + 3) * KK], a3);
        }
        red[sl][o] = (a0 + a1) + (a2 + a3);
    }
    __syncthreads();
    if (sl == 0) {
        float a = red[0][o] + red[1][o] + red[2][o] + red[3][o] + b1[o];
        float sg = 1.0f / (1.0f + __expf(-a));
        hs[o] = a * sg;                          // SiLU
    }
    __syncthreads();

    // layer 2
    {
        const float* wc = w2 + (sl * 32) * KK + o;
        const float* hc = hs + sl * 32;
        float a0 = 0.f, a1 = 0.f, a2 = 0.f, a3 = 0.f;
        #pragma unroll
        for (int kk = 0; kk < 32; kk += 4) {
            a0 = fmaf(hc[kk + 0], wc[(kk + 0) * KK], a0);
            a1 = fmaf(hc[kk + 1], wc[(kk + 1) * KK], a1);
            a2 = fmaf(hc[kk + 2], wc[(kk + 2) * KK], a2);
            a3 = fmaf(hc[kk + 3], wc[(kk + 3) * KK], a3);
        }
        red[sl][o] = (a0 + a1) + (a2 + a3);
    }
    __syncthreads();
    if (sl == 0) {
        float oo = (red[0][o] + red[1][o] + red[2][o] + red[3][o] + b2[o]) * 2.0f;
        if (c < 2) g_t2[c][o] = oo; else g_t02[o] = oo;
    }
}

// ---------------------------------------------------------------------------
// Kernel 2: main edge kernel — one block per (b,i) row, 128 threads (4 warps).
// Small blocks keep the whole 1024-block grid resident in ONE wave (no tail).
// ---------------------------------------------------------------------------
__global__ void __launch_bounds__(128) edge_kernel(
    const float* __restrict__ pos,
    const int*   __restrict__ nte,
    const void*  __restrict__ pad_m,
    const void*  __restrict__ aa_m,
    const void*  __restrict__ pos_m,
    const float* __restrict__ means,
    const float* __restrict__ stds,
    const float* __restrict__ mul_w,
    const float* __restrict__ bias_w,
    float* __restrict__ out)
{
    const int i = blockIdx.x;
    const int b = blockIdx.y;
    const int tid  = threadIdx.x;
    const int lane = tid & 31;
    const int warp = tid >> 5;
    const int isb  = g_mask_is_byte;

    __shared__ float4 pk[NN];            // (x, padf, mdf, -)   8KB
    __shared__ float  ppos[NN * 3];      //                     6KB
    __shared__ float2 tbl[NEDGE];        // (mul, bias)        12KB
    __shared__ float4 partial[4][32];    //                     2KB

    for (int idx = tid; idx < NN * 3; idx += 128) ppos[idx] = pos[b * NN * 3 + idx];
    for (int idx = tid; idx < NEDGE; idx += 128)
        tbl[idx] = make_float2(mul_w[idx], bias_w[idx]);
    __syncthreads();

    const float pix = ppos[i * 3 + 0], piy = ppos[i * 3 + 1], piz = ppos[i * 3 + 2];
    const int aa_i = maskv(aa_m,  b * NN + i, isb);
    const int mp_i = maskv(pos_m, b * NN + i, isb);

    float* dpo = out + OFF_DP + ((size_t)(b * NN + i)) * (size_t)NN * 3;
    const int2* nrow = (const int2*)(nte + ((size_t)(b * NN + i)) * (size_t)NN * 2);

    // ---- Phase 1: per-j scalars -------------------------------------------
    #pragma unroll
    for (int jt = tid; jt < NN; jt += 128) {
        float dx = ppos[jt * 3 + 0] - pix;
        float dy = ppos[jt * 3 + 1] - piy;
        float dz = ppos[jt * 3 + 2] - piz;
        float dist = sqrtf(dx * dx + dy * dy + dz * dz);
        float rinv = __fdividef(1.0f, dist + 1e-5f);
        dpo[jt * 3 + 0] = dx * rinv;
        dpo[jt * 3 + 1] = dy * rinv;
        dpo[jt * 3 + 2] = dz * rinv;

        int2 e2  = nrow[jt];
        int aa_j = maskv(aa_m, b * NN + jt, isb);
        float2 t0 = tbl[aa_i ? 0 : e2.x];
        float2 t1 = tbl[aa_j ? 0 : e2.y];
        float mul = t0.x + t1.x;
        float bia = t0.y + t1.y;

        int padj = maskv(pad_m, b * NN + jt, isb);
        int md   = mp_i | maskv(pos_m, b * NN + jt, isb);
        pk[jt] = make_float4(fmaf(mul, dist, bia),
                             padj ? 0.0f : 1.0f,
                             md   ? 1.0f : 0.0f, 0.0f);
    }
    __syncthreads();

    // ---- per-thread k-quad parameters -------------------------------------
    const int k0 = lane * 4;
    float4 mn = *(const float4*)(means + k0);
    float4 sd = *(const float4*)(stds + k0);
    float is_x = 1.0f / (fabsf(sd.x) + 0.01f);
    float is_y = 1.0f / (fabsf(sd.y) + 0.01f);
    float is_z = 1.0f / (fabsf(sd.z) + 0.01f);
    float is_w = 1.0f / (fabsf(sd.w) + 0.01f);
    const float inv_a = 0.39894290f;           // 1/sqrt(2*3.14159)
    float cf_x = is_x * inv_a, cf_y = is_y * inv_a, cf_z = is_z * inv_a, cf_w = is_w * inv_a;
    float mi_x = mn.x * is_x, mi_y = mn.y * is_y, mi_z = mn.z * is_z, mi_w = mn.w * is_w;

    float4 t2v  = *(const float4*)(&g_t2[b][k0]);
    float4 t02v = *(const float4*)(&g_t02[k0]);
    float dt_x = t2v.x - t02v.x, dt_y = t2v.y - t02v.y;
    float dt_z = t2v.z - t02v.z, dt_w = t2v.w - t02v.w;

    float* efb = out + OFF_EF + ((size_t)(b * NN + i)) * (size_t)(NN * KK);
    float4 acc = make_float4(0.f, 0.f, 0.f, 0.f);
    const float4 zero4 = make_float4(0.f, 0.f, 0.f, 0.f);

    // ---- Phase 2: warp owns j%4, lane owns k-quad. Branch is warp-uniform. --
    #pragma unroll 8
    for (int jb = 0; jb < NN / 4; jb++) {
        int j = jb * 4 + warp;
        float4 p = pk[j];
        float4* dst = (float4*)(efb + (size_t)j * KK + k0);

        if (p.y == 0.0f) {
            // padded j-column: entire K row is zero — skip all math
            __stcs(dst, zero4);
        } else {
            float x = p.x, mdf = p.z;

            float zx = fmaf(x, is_x, -mi_x);
            float zy = fmaf(x, is_y, -mi_y);
            float zz = fmaf(x, is_z, -mi_z);
            float zw = fmaf(x, is_w, -mi_w);
            float gx = __expf(zx * zx * -0.5f);
            float gy = __expf(zy * zy * -0.5f);
            float gz = __expf(zz * zz * -0.5f);
            float gw = __expf(zw * zw * -0.5f);

            float4 r;
            r.x = fmaf(gx, cf_x, fmaf(mdf, dt_x, t02v.x));
            r.y = fmaf(gy, cf_y, fmaf(mdf, dt_y, t02v.y));
            r.z = fmaf(gz, cf_z, fmaf(mdf, dt_z, t02v.z));
            r.w = fmaf(gw, cf_w, fmaf(mdf, dt_w, t02v.w));

            acc.x += r.x; acc.y += r.y; acc.z += r.z; acc.w += r.w;
            __stcs(dst, r);
        }
    }

    // ---- row-sum reduction across the 4 warps ------------------------------
    partial[warp][lane] = acc;
    __syncthreads();
    if (warp == 0) {
        float4 a0 = partial[0][lane], a1 = partial[1][lane];
        float4 a2 = partial[2][lane], a3 = partial[3][lane];
        float4 s = make_float4(a0.x + a1.x + a2.x + a3.x,
                               a0.y + a1.y + a2.y + a3.y,
                               a0.z + a1.z + a2.z + a3.z,
                               a0.w + a1.w + a2.w + a3.w);
        *(float4*)(&g_sum[((size_t)(b * NN + i)) * KK + k0]) = s;
    }
}

// ---------------------------------------------------------------------------
// Kernel 3: merge = sum_edge_features @ proj_w + proj_b (zero padded rows)
// ---------------------------------------------------------------------------
__global__ void __launch_bounds__(256) proj_kernel(
    const float* __restrict__ pw, const float* __restrict__ pb,
    const void* __restrict__ pad_m, float* __restrict__ out)
{
    __shared__ float s[16 * KK];
    const int bx  = blockIdx.x;
    const int e   = blockIdx.y * 256 + threadIdx.x;
    const int tid = threadIdx.x;

    for (int idx = tid; idx < 16 * KK; idx += 256)
        s[idx] = g_sum[(size_t)bx * 16 * KK + idx];
    __syncthreads();

    float acc[16];
    #pragma unroll
    for (int ii = 0; ii < 16; ii++) acc[ii] = 0.0f;

    for (int k = 0; k < KK; k++) {
        float w = pw[(size_t)k * EE + e];
        #pragma unroll
        for (int ii = 0; ii < 16; ii++) acc[ii] = fmaf(s[ii * KK + k], w, acc[ii]);
    }

    float bias = pb[e];
    int isb = g_mask_is_byte;
    #pragma unroll
    for (int ii = 0; ii < 16; ii++) {
        int row = bx * 16 + ii;                      // row = b*N + i
        int pm = maskv(pad_m, row, isb);
        out[OFF_MERGE + (size_t)row * EE + e] = pm ? 0.0f : (acc[ii] + bias);
    }
}

// ---------------------------------------------------------------------------
extern "C" void kernel_launch(void* const* d_in, const int* in_sizes, int n_in,
                              void* d_out, int out_size)
{
    const float* pos    = (const float*)d_in[0];
    const int*   nte    = (const int*)  d_in[1];
    const void*  pad_m  = d_in[2];
    const void*  aa_m   = d_in[3];
    const void*  pos_m  = d_in[4];
    const int*   time_p = (const int*)  d_in[5];
    const float* means  = (const float*)d_in[6];
    const float* stds   = (const float*)d_in[7];
    const float* mul_w  = (const float*)d_in[8];
    const float* bias_w = (const float*)d_in[9];
    const float* proj_w = (const float*)d_in[10];
    const float* proj_b = (const float*)d_in[11];
    const float* t_w1   = (const float*)d_in[12];
    const float* t_b1   = (const float*)d_in[13];
    const float* t_w2   = (const float*)d_in[14];
    const float* t_b2   = (const float*)d_in[15];
    float* out = (float*)d_out;

    tenc_kernel<<<3, 512>>>(time_p, t_w1, t_b1, t_w2, t_b2, pad_m);
    edge_kernel<<<dim3(NN, BB), 128>>>(pos, nte, pad_m, aa_m, pos_m,
                                       means, stds, mul_w, bias_w, out);
    proj_kernel<<<dim3((BB * NN) / 16, EE / 256), 256>>>(proj_w, proj_b, pad_m, out);
}

// round 6
// speedup vs baseline: 1.6047x; 1.0726x over previous
#include <cuda_runtime.h>
#include <cstdint>
#include <cstddef>

#define BB 2
#define NN 512
#define KK 128
#define EE 768
#define NEDGE 1536

// output layout: edge_feature [B,N,N,K] | merge [B,N,E] | delta_pos [B,N,N,3]
#define OFF_EF    ((size_t)0)
#define OFF_MERGE ((size_t)BB*NN*NN*KK)                 // 67108864
#define OFF_DP    (OFF_MERGE + (size_t)BB*NN*EE)        // 67895296

__device__ __align__(16) float g_t2[BB][KK];   // 2 * t_enc(time_pos[b])
__device__ __align__(16) float g_t02[KK];      // 2 * t_enc(0)
__device__ __align__(16) float g_sum[BB*NN*KK];
__device__ int g_mask_is_byte;

__device__ __forceinline__ int maskv(const void* p, int idx, int isb) {
    return isb ? (int)((const unsigned char*)p)[idx] : ((const int*)p)[idx];
}

// ---------------------------------------------------------------------------
// Kernel 1: timestep encoder MLP.
// grid = 3 (c = t(b0), t(b1), t(0)), block = 512.
// thread: o = tid & 127 (output col), sl = tid >> 7 (k-slice of 32).
// KEY: w2's column chunk is loaded into registers BEFORE layer-1 compute, so
// both layers' weights stream from DRAM concurrently -> ONE latency trip.
// ---------------------------------------------------------------------------
__global__ void __launch_bounds__(512) tenc_kernel(
    const int* __restrict__ time_pos,
    const float* __restrict__ w1, const float* __restrict__ b1,
    const float* __restrict__ w2, const float* __restrict__ b2,
    const void* __restrict__ pad_mask)
{
    __shared__ float es[KK], hs[KK];
    __shared__ float red[4][KK];
    const int tid = threadIdx.x;
    const int c  = blockIdx.x;
    const int o  = tid & 127;
    const int sl = tid >> 7;

    // mask-format detection: bool-as-bytes -> some 32-bit word in first 1KB > 1
    {
        int f = 0;
        if (tid < 256) f = (((const unsigned int*)pad_mask)[tid] > 1u);
        int any = __syncthreads_or(f);
        if (tid == 0 && c == 0) g_mask_is_byte = any ? 1 : 0;
    }

    // prefetch w2 column chunk into registers (independent of layer 1)
    float w2r[32];
    {
        const float* wc2 = w2 + (sl * 32) * KK + o;
        #pragma unroll
        for (int kk = 0; kk < 32; kk++) w2r[kk] = wc2[kk * KK];
    }

    if (tid < KK) {
        float tval = (c < 2) ? (float)time_pos[c] : 0.0f;
        int h = (tid < 64) ? tid : tid - 64;
        float fr  = __expf(-9.210340371976184f * (float)h * (1.0f / 64.0f));
        float arg = tval * fr;
        es[tid] = (tid < 64) ? cosf(arg) : sinf(arg);
    }
    __syncthreads();

    // layer 1: hs[o] = silu(es . w1[:,o] + b1[o])
    {
        const float* wc = w1 + (sl * 32) * KK + o;
        const float* ec = es + sl * 32;
        float a0 = 0.f, a1 = 0.f, a2 = 0.f, a3 = 0.f;
        #pragma unroll
        for (int kk = 0; kk < 32; kk += 4) {
            a0 = fmaf(ec[kk + 0], wc[(kk + 0) * KK], a0);
            a1 = fmaf(ec[kk + 1], wc[(kk + 1) * KK], a1);
            a2 = fmaf(ec[kk + 2], wc[(kk + 2) * KK], a2);
            a3 = fmaf(ec[kk + 3], wc[(kk + 3) * KK], a3);
        }
        red[sl][o] = (a0 + a1) + (a2 + a3);
    }
    __syncthreads();
    if (sl == 0) {
        float a = red[0][o] + red[1][o] + red[2][o] + red[3][o] + b1[o];
        float sg = 1.0f / (1.0f + __expf(-a));
        hs[o] = a * sg;                          // SiLU
    }
    __syncthreads();

    // layer 2: pure register FMA against prefetched w2r
    {
        const float* hc = hs + sl * 32;
        float a0 = 0.f, a1 = 0.f, a2 = 0.f, a3 = 0.f;
        #pragma unroll
        for (int kk = 0; kk < 32; kk += 4) {
            a0 = fmaf(hc[kk + 0], w2r[kk + 0], a0);
            a1 = fmaf(hc[kk + 1], w2r[kk + 1], a1);
            a2 = fmaf(hc[kk + 2], w2r[kk + 2], a2);
            a3 = fmaf(hc[kk + 3], w2r[kk + 3], a3);
        }
        red[sl][o] = (a0 + a1) + (a2 + a3);
    }
    __syncthreads();
    if (sl == 0) {
        float oo = (red[0][o] + red[1][o] + red[2][o] + red[3][o] + b2[o]) * 2.0f;
        if (c < 2) g_t2[c][o] = oo; else g_t02[o] = oo;
    }
}

// ---------------------------------------------------------------------------
// Kernel 2: main edge kernel — one block per (b,i) row, 128 threads (4 warps).
// Whole 1024-block grid resident in ONE wave.
// ---------------------------------------------------------------------------
__global__ void __launch_bounds__(128) edge_kernel(
    const float* __restrict__ pos,
    const int*   __restrict__ nte,
    const void*  __restrict__ pad_m,
    const void*  __restrict__ aa_m,
    const void*  __restrict__ pos_m,
    const float* __restrict__ means,
    const float* __restrict__ stds,
    const float* __restrict__ mul_w,
    const float* __restrict__ bias_w,
    float* __restrict__ out)
{
    const int i = blockIdx.x;
    const int b = blockIdx.y;
    const int tid  = threadIdx.x;
    const int lane = tid & 31;
    const int warp = tid >> 5;
    const int isb  = g_mask_is_byte;

    __shared__ float4 pk[NN];            // (x, padf, mdf, -)   8KB
    __shared__ float  ppos[NN * 3];      //                     6KB
    __shared__ float2 tbl[NEDGE];        // (mul, bias)        12KB
    __shared__ float4 partial[4][32];    //                     2KB

    // vectorized prologue: few wide LDGs (reduces front-batched L1tex queueing)
    {
        const float4* p4 = (const float4*)(pos + b * NN * 3);   // 384 float4
        float4* s4 = (float4*)ppos;
        for (int idx = tid; idx < 384; idx += 128) s4[idx] = p4[idx];

        const float4* m4 = (const float4*)mul_w;                // 384 float4
        const float4* b4 = (const float4*)bias_w;
        for (int idx = tid; idx < 384; idx += 128) {
            float4 m = m4[idx], bb = b4[idx];
            tbl[idx * 4 + 0] = make_float2(m.x, bb.x);
            tbl[idx * 4 + 1] = make_float2(m.y, bb.y);
            tbl[idx * 4 + 2] = make_float2(m.z, bb.z);
            tbl[idx * 4 + 3] = make_float2(m.w, bb.w);
        }
    }
    __syncthreads();

    const float pix = ppos[i * 3 + 0], piy = ppos[i * 3 + 1], piz = ppos[i * 3 + 2];
    const int aa_i = maskv(aa_m,  b * NN + i, isb);
    const int mp_i = maskv(pos_m, b * NN + i, isb);

    float* dpo = out + OFF_DP + ((size_t)(b * NN + i)) * (size_t)NN * 3;
    const int4* nrow4 = (const int4*)(nte + ((size_t)(b * NN + i)) * (size_t)NN * 2);

    // ---- Phase 1: per-j scalars (2 j's per iter via int4 edge loads) -------
    #pragma unroll
    for (int jt2 = tid; jt2 < NN / 2; jt2 += 128) {
        int4 e4 = nrow4[jt2];
        #pragma unroll
        for (int h = 0; h < 2; h++) {
            int jt = jt2 * 2 + h;
            float dx = ppos[jt * 3 + 0] - pix;
            float dy = ppos[jt * 3 + 1] - piy;
            float dz = ppos[jt * 3 + 2] - piz;
            float dist = sqrtf(dx * dx + dy * dy + dz * dz);
            float rinv = __fdividef(1.0f, dist + 1e-5f);
            dpo[jt * 3 + 0] = dx * rinv;
            dpo[jt * 3 + 1] = dy * rinv;
            dpo[jt * 3 + 2] = dz * rinv;

            int exi = h ? e4.z : e4.x;
            int eyi = h ? e4.w : e4.y;
            int aa_j = maskv(aa_m, b * NN + jt, isb);
            float2 t0 = tbl[aa_i ? 0 : exi];
            float2 t1 = tbl[aa_j ? 0 : eyi];
            float mul = t0.x + t1.x;
            float bia = t0.y + t1.y;

            int padj = maskv(pad_m, b * NN + jt, isb);
            int md   = mp_i | maskv(pos_m, b * NN + jt, isb);
            pk[jt] = make_float4(fmaf(mul, dist, bia),
                                 padj ? 0.0f : 1.0f,
                                 md   ? 1.0f : 0.0f, 0.0f);
        }
    }
    __syncthreads();

    // ---- per-thread k-quad parameters -------------------------------------
    const int k0 = lane * 4;
    float4 mn = *(const float4*)(means + k0);
    float4 sd = *(const float4*)(stds + k0);
    float is_x = 1.0f / (fabsf(sd.x) + 0.01f);
    float is_y = 1.0f / (fabsf(sd.y) + 0.01f);
    float is_z = 1.0f / (fabsf(sd.z) + 0.01f);
    float is_w = 1.0f / (fabsf(sd.w) + 0.01f);
    const float inv_a = 0.39894290f;           // 1/sqrt(2*3.14159)
    float cf_x = is_x * inv_a, cf_y = is_y * inv_a, cf_z = is_z * inv_a, cf_w = is_w * inv_a;
    float mi_x = mn.x * is_x, mi_y = mn.y * is_y, mi_z = mn.z * is_z, mi_w = mn.w * is_w;

    float4 t2v  = *(const float4*)(&g_t2[b][k0]);
    float4 t02v = *(const float4*)(&g_t02[k0]);
    float dt_x = t2v.x - t02v.x, dt_y = t2v.y - t02v.y;
    float dt_z = t2v.z - t02v.z, dt_w = t2v.w - t02v.w;

    float* efb = out + OFF_EF + ((size_t)(b * NN + i)) * (size_t)(NN * KK);
    float4 acc = make_float4(0.f, 0.f, 0.f, 0.f);
    const float4 zero4 = make_float4(0.f, 0.f, 0.f, 0.f);

    // ---- Phase 2: warp owns j%4, lane owns k-quad. Branch is warp-uniform. --
    #pragma unroll 8
    for (int jb = 0; jb < NN / 4; jb++) {
        int j = jb * 4 + warp;
        float4 p = pk[j];
        float4* dst = (float4*)(efb + (size_t)j * KK + k0);

        if (p.y == 0.0f) {
            __stcs(dst, zero4);               // padded j: whole K row zero
        } else {
            float x = p.x, mdf = p.z;

            float zx = fmaf(x, is_x, -mi_x);
            float zy = fmaf(x, is_y, -mi_y);
            float zz = fmaf(x, is_z, -mi_z);
            float zw = fmaf(x, is_w, -mi_w);
            float gx = __expf(zx * zx * -0.5f);
            float gy = __expf(zy * zy * -0.5f);
            float gz = __expf(zz * zz * -0.5f);
            float gw = __expf(zw * zw * -0.5f);

            float4 r;
            r.x = fmaf(gx, cf_x, fmaf(mdf, dt_x, t02v.x));
            r.y = fmaf(gy, cf_y, fmaf(mdf, dt_y, t02v.y));
            r.z = fmaf(gz, cf_z, fmaf(mdf, dt_z, t02v.z));
            r.w = fmaf(gw, cf_w, fmaf(mdf, dt_w, t02v.w));

            acc.x += r.x; acc.y += r.y; acc.z += r.z; acc.w += r.w;
            __stcs(dst, r);
        }
    }

    // ---- row-sum reduction across the 4 warps ------------------------------
    partial[warp][lane] = acc;
    __syncthreads();
    if (warp == 0) {
        float4 a0 = partial[0][lane], a1 = partial[1][lane];
        float4 a2 = partial[2][lane], a3 = partial[3][lane];
        float4 s = make_float4(a0.x + a1.x + a2.x + a3.x,
                               a0.y + a1.y + a2.y + a3.y,
                               a0.z + a1.z + a2.z + a3.z,
                               a0.w + a1.w + a2.w + a3.w);
        *(float4*)(&g_sum[((size_t)(b * NN + i)) * KK + k0]) = s;
    }
}

// ---------------------------------------------------------------------------
// Kernel 3: merge = sum_edge_features @ proj_w + proj_b (zero padded rows).
// s tile stored TRANSPOSED (stride 20 pad) -> 4 broadcast LDS.128 per k.
// ---------------------------------------------------------------------------
__global__ void __launch_bounds__(256) proj_kernel(
    const float* __restrict__ pw, const float* __restrict__ pb,
    const void* __restrict__ pad_m, float* __restrict__ out)
{
    __shared__ __align__(16) float s_t[KK * 20];   // [k][ii] padded
    const int bx  = blockIdx.x;
    const int e   = blockIdx.y * 256 + threadIdx.x;
    const int tid = threadIdx.x;

    for (int idx = tid; idx < 16 * KK; idx += 256) {
        int row = idx >> 7;          // 0..15
        int k   = idx & 127;
        s_t[k * 20 + row] = g_sum[(size_t)bx * 16 * KK + idx];
    }
    __syncthreads();

    float acc[16];
    #pragma unroll
    for (int ii = 0; ii < 16; ii++) acc[ii] = 0.0f;

    #pragma unroll 4
    for (int k = 0; k < KK; k++) {
        float w = pw[(size_t)k * EE + e];
        const float4* rowp = (const float4*)(s_t + k * 20);
        #pragma unroll
        for (int q = 0; q < 4; q++) {
            float4 sv = rowp[q];
            acc[q * 4 + 0] = fmaf(sv.x, w, acc[q * 4 + 0]);
            acc[q * 4 + 1] = fmaf(sv.y, w, acc[q * 4 + 1]);
            acc[q * 4 + 2] = fmaf(sv.z, w, acc[q * 4 + 2]);
            acc[q * 4 + 3] = fmaf(sv.w, w, acc[q * 4 + 3]);
        }
    }

    float bias = pb[e];
    int isb = g_mask_is_byte;
    #pragma unroll
    for (int ii = 0; ii < 16; ii++) {
        int row = bx * 16 + ii;                      // row = b*N + i
        int pm = maskv(pad_m, row, isb);
        out[OFF_MERGE + (size_t)row * EE + e] = pm ? 0.0f : (acc[ii] + bias);
    }
}

// ---------------------------------------------------------------------------
extern "C" void kernel_launch(void* const* d_in, const int* in_sizes, int n_in,
                              void* d_out, int out_size)
{
    const float* pos    = (const float*)d_in[0];
    const int*   nte    = (const int*)  d_in[1];
    const void*  pad_m  = d_in[2];
    const void*  aa_m   = d_in[3];
    const void*  pos_m  = d_in[4];
    const int*   time_p = (const int*)  d_in[5];
    const float* means  = (const float*)d_in[6];
    const float* stds   = (const float*)d_in[7];
    const float* mul_w  = (const float*)d_in[8];
    const float* bias_w = (const float*)d_in[9];
    const float* proj_w = (const float*)d_in[10];
    const float* proj_b = (const float*)d_in[11];
    const float* t_w1   = (const float*)d_in[12];
    const float* t_b1   = (const float*)d_in[13];
    const float* t_w2   = (const float*)d_in[14];
    const float* t_b2   = (const float*)d_in[15];
    float* out = (float*)d_out;

    tenc_kernel<<<3, 512>>>(time_p, t_w1, t_b1, t_w2, t_b2, pad_m);
    edge_kernel<<<dim3(NN, BB), 128>>>(pos, nte, pad_m, aa_m, pos_m,
                                       means, stds, mul_w, bias_w, out);
    proj_kernel<<<dim3((BB * NN) / 16, EE / 256), 256>>>(proj_w, proj_b, pad_m, out);
}